// round 11
// baseline (speedup 1.0000x reference)
#include <cuda_runtime.h>
#include <math.h>

#define L_LAYERS 32
#define BEAM 8
#define KV2 2
#define HEADS 8
#define SEQ 1024
#define HDIM 64
#define VOCAB 50257
#define HIST 128
#define TOPK 8
#define CHUNKS 32
#define CHUNK_SZ 1571          // 32*1571 = 50272 >= 50257

// per-(l,b) slab: KV2*HEADS*SEQ*HDIM floats = 1,048,576 floats = 262,144 float4
#define SLAB_F4 262144
#define SEG_F4 2048            // 32KB segment per block-iteration
#define SEGS_PER_SLAB 128      // 262144 / 2048
#define NCHUNK (L_LAYERS * SEGS_PER_SLAB)   // 4096 (layer,offset) chunks
#define NSEG (NCHUNK * BEAM)                // 32768 total segments
#define GATHER_GRID (148 * 8)               // persistent-ish grid

// output offsets (float32 elements, concatenated in reference return order)
#define OFF_KV   0LL
#define OFF_SAVE 268435456LL
#define OFF_PROB 268436488LL
#define OFF_TBI  268436496LL
#define OFF_MAX  268436504LL

// device-global scratch (no allocations allowed)
__device__ float g_part_m[BEAM * CHUNKS];
__device__ float g_part_s[BEAM * CHUNKS];
__device__ float g_part_val[BEAM * CHUNKS * TOPK];
__device__ int   g_part_idx[BEAM * CHUNKS * TOPK];
__device__ int   g_beam_index[BEAM];

__device__ __forceinline__ bool cand_gt(float av, int ai, float bv, int bi) {
    // strictly greater value wins; on exact tie, lower index wins (jax.lax.top_k order)
    return (av > bv) || (av == bv && ai < bi);
}

// ---------------------------------------------------------------------------
// Kernel 1: per-chunk online softmax (m, s) + top-8. (measured 26.5us)
// grid = BEAM*CHUNKS = 256 blocks, 128 threads.
// ---------------------------------------------------------------------------
__global__ void __launch_bounds__(128) chunk_topk_kernel(const float* __restrict__ logits) {
    const int chunk = blockIdx.x & (CHUNKS - 1);
    const int r     = blockIdx.x >> 5;
    const int tid   = threadIdx.x;
    const int start = chunk * CHUNK_SZ;
    const int end   = min(start + CHUNK_SZ, VOCAB);
    const float* row = logits + (long long)r * VOCAB;

    float m = -INFINITY, s = 0.0f;
    float lv[TOPK];
    int   li[TOPK];
#pragma unroll
    for (int j = 0; j < TOPK; j++) { lv[j] = -INFINITY; li[j] = 0x7fffffff; }

    for (int i = start + tid; i < end; i += 128) {
        float v = row[i];
        if (v > m) { s = s * __expf(m - v) + 1.0f; m = v; }
        else       { s += __expf(v - m); }
        if (cand_gt(v, i, lv[TOPK - 1], li[TOPK - 1])) {
            int j = TOPK - 1;
            while (j > 0 && cand_gt(v, i, lv[j - 1], li[j - 1])) {
                lv[j] = lv[j - 1]; li[j] = li[j - 1]; j--;
            }
            lv[j] = v; li[j] = i;
        }
    }

    __shared__ float sm[128], ss[128];
    sm[tid] = m; ss[tid] = s;
    __syncthreads();
    for (int st = 64; st > 0; st >>= 1) {
        if (tid < st) {
            float m1 = sm[tid], s1 = ss[tid];
            float m2 = sm[tid + st], s2 = ss[tid + st];
            float M = fmaxf(m1, m2);
            float S = ((m1 > -INFINITY) ? s1 * __expf(m1 - M) : 0.0f)
                    + ((m2 > -INFINITY) ? s2 * __expf(m2 - M) : 0.0f);
            sm[tid] = M; ss[tid] = S;
        }
        __syncthreads();
    }

    __shared__ float sv[128 * TOPK];
    __shared__ int   si[128 * TOPK];
#pragma unroll
    for (int j = 0; j < TOPK; j++) { sv[tid * TOPK + j] = lv[j]; si[tid * TOPK + j] = li[j]; }
    __syncthreads();

    for (int step = 1; step < 128; step <<= 1) {
        if ((tid & (2 * step - 1)) == 0) {
            float* A  = &sv[tid * TOPK];
            int*   Ai = &si[tid * TOPK];
            float* B  = &sv[(tid + step) * TOPK];
            int*   Bi = &si[(tid + step) * TOPK];
            float mv[TOPK]; int mi[TOPK];
            int pa = 0, pb = 0;
#pragma unroll
            for (int j = 0; j < TOPK; j++) {
                if (cand_gt(A[pa], Ai[pa], B[pb], Bi[pb])) { mv[j] = A[pa]; mi[j] = Ai[pa]; pa++; }
                else                                        { mv[j] = B[pb]; mi[j] = Bi[pb]; pb++; }
            }
#pragma unroll
            for (int j = 0; j < TOPK; j++) { A[j] = mv[j]; Ai[j] = mi[j]; }
        }
        __syncthreads();
    }

    if (tid == 0) {
        g_part_m[blockIdx.x] = sm[0];
        g_part_s[blockIdx.x] = ss[0];
    }
    if (tid < TOPK) {
        g_part_val[blockIdx.x * TOPK + tid] = sv[tid];
        g_part_idx[blockIdx.x * TOPK + tid] = si[tid];
    }
}

// ---------------------------------------------------------------------------
// Kernel 2: per-row merge (LSE + top-8), global beam top-8, small outputs.
// ---------------------------------------------------------------------------
__global__ void select_kernel(const int* __restrict__ save_id,
                              const float* __restrict__ prev_prob,
                              float* __restrict__ out) {
    __shared__ float cv[BEAM * TOPK];
    __shared__ int   ci[BEAM * TOPK];
    __shared__ int   s_beam[BEAM];
    __shared__ int   s_tbi[BEAM];
    __shared__ float s_prob[BEAM];

    const int tid = threadIdx.x;

    if (tid < BEAM) {
        const int r = tid;
        float M = -INFINITY;
        for (int c = 0; c < CHUNKS; c++) M = fmaxf(M, g_part_m[r * CHUNKS + c]);
        float S = 0.0f;
        for (int c = 0; c < CHUNKS; c++) {
            float pm = g_part_m[r * CHUNKS + c];
            if (pm > -INFINITY) S += g_part_s[r * CHUNKS + c] * __expf(pm - M);
        }
        const float lse = M + logf(S);

        const float* pv = &g_part_val[r * CHUNKS * TOPK];
        const int*   pi = &g_part_idx[r * CHUNKS * TOPK];
        int chosen[TOPK];
        for (int k = 0; k < TOPK; k++) {
            int best = -1;
            float bv = -INFINITY; int bidx = 0x7fffffff;
            for (int i = 0; i < CHUNKS * TOPK; i++) {
                bool skip = false;
                for (int p = 0; p < k; p++) if (chosen[p] == i) { skip = true; break; }
                if (skip) continue;
                if (best < 0 || cand_gt(pv[i], pi[i], bv, bidx)) {
                    best = i; bv = pv[i]; bidx = pi[i];
                }
            }
            chosen[k] = best;
            cv[r * TOPK + k] = bv - lse + prev_prob[r];
            ci[r * TOPK + k] = bidx;
        }
    }
    __syncthreads();

    if (tid == 0) {
        bool used[BEAM * TOPK];
        for (int i = 0; i < BEAM * TOPK; i++) used[i] = false;
        for (int b = 0; b < BEAM; b++) {
            int best = -1;
            for (int i = 0; i < BEAM * TOPK; i++) {
                if (used[i]) continue;
                if (best < 0 || cv[i] > cv[best]) best = i;
            }
            used[best] = true;
            s_beam[b] = best >> 3;
            s_tbi[b]  = ci[best];
            s_prob[b] = cv[best];
            g_beam_index[b] = best >> 3;
        }
    }
    __syncthreads();

    for (int i = tid; i < BEAM * (HIST + 1); i += blockDim.x) {
        int b = i / (HIST + 1);
        int c = i % (HIST + 1);
        int val = (c < HIST) ? save_id[s_beam[b] * HIST + c] : s_tbi[b];
        out[OFF_SAVE + i] = (float)val;
    }
    if (tid < BEAM) {
        out[OFF_PROB + tid] = s_prob[tid];
        out[OFF_TBI + tid]  = (float)s_tbi[tid];
    }
    if (tid == 0) out[OFF_MAX] = (float)s_tbi[0];
}

// ---------------------------------------------------------------------------
// Kernel 3: persistent grid-stride gather, MLP=8.
// Each iteration: one 32KB segment (2048 float4) = 8 independent float4 per
// thread, loads batched before stores. grid = 1184 blocks x 256 threads;
// each block runs ~28 independent iterations (ptxas can overlap across them).
// Segment order is beam-innermost (free; enables L2 merging if duplicate
// sources ever occur).
// ---------------------------------------------------------------------------
__global__ void __launch_bounds__(256) gather_kernel(const float4* __restrict__ kv,
                                                     float4* __restrict__ out) {
    __shared__ int bi[BEAM];
    if (threadIdx.x < BEAM) bi[threadIdx.x] = g_beam_index[threadIdx.x];
    __syncthreads();

    for (int seg = blockIdx.x; seg < NSEG; seg += GATHER_GRID) {
        const int b     = seg & 7;                 // beam innermost
        const int chunk = seg >> 3;                // 0..4095
        const int c     = chunk & (SEGS_PER_SLAB - 1);
        const int l     = chunk >> 7;

        const long long off  = (long long)c * SEG_F4 + threadIdx.x;
        const float4* src = kv  + ((long long)(l * BEAM + bi[b]) * SLAB_F4 + off);
        float4*       dst = out + ((long long)(l * BEAM + b)     * SLAB_F4 + off);

        float4 v0 = src[0 * 256];
        float4 v1 = src[1 * 256];
        float4 v2 = src[2 * 256];
        float4 v3 = src[3 * 256];
        float4 v4 = src[4 * 256];
        float4 v5 = src[5 * 256];
        float4 v6 = src[6 * 256];
        float4 v7 = src[7 * 256];
        dst[0 * 256] = v0;
        dst[1 * 256] = v1;
        dst[2 * 256] = v2;
        dst[3 * 256] = v3;
        dst[4 * 256] = v4;
        dst[5 * 256] = v5;
        dst[6 * 256] = v6;
        dst[7 * 256] = v7;
    }
}

// ---------------------------------------------------------------------------
extern "C" void kernel_launch(void* const* d_in, const int* in_sizes, int n_in,
                              void* d_out, int out_size) {
    const float* kv_cache  = (const float*)d_in[0];
    const float* logits    = (const float*)d_in[1];
    const int*   save_id   = (const int*)d_in[2];
    const float* prev_prob = (const float*)d_in[3];
    float* out = (float*)d_out;

    chunk_topk_kernel<<<BEAM * CHUNKS, 128>>>(logits);
    select_kernel<<<1, 256>>>(save_id, prev_prob, out);
    gather_kernel<<<GATHER_GRID, 256>>>(
        (const float4*)kv_cache, (float4*)(out + OFF_KV));
}

// round 13
// speedup vs baseline: 1.0731x; 1.0731x over previous
#include <cuda_runtime.h>
#include <math.h>

#define L_LAYERS 32
#define BEAM 8
#define KV2 2
#define HEADS 8
#define SEQ 1024
#define HDIM 64
#define VOCAB 50257
#define HIST 128
#define TOPK 8
#define CHUNKS 32
#define CHUNK_SZ 1571          // 32*1571 = 50272 >= 50257
#define K1_THREADS 256

// per-(l,b) slab: KV2*HEADS*SEQ*HDIM floats = 1,048,576 floats = 262,144 float4
#define SLAB_F4 262144
#define GRPS_PER_LAYER 256     // 262144 f4 / 1024 f4 per block
#define CHUNK_GLOBAL (L_LAYERS * GRPS_PER_LAYER)   // 8192

// output offsets (float32 elements, concatenated in reference return order)
#define OFF_KV   0LL
#define OFF_SAVE 268435456LL
#define OFF_PROB 268436488LL
#define OFF_TBI  268436496LL
#define OFF_MAX  268436504LL

// device-global scratch (no allocations allowed)
__device__ float g_part_m[BEAM * CHUNKS];
__device__ float g_part_s[BEAM * CHUNKS];
__device__ float g_part_val[BEAM * CHUNKS * TOPK];
__device__ int   g_part_idx[BEAM * CHUNKS * TOPK];
__device__ int   g_beam_index[BEAM];
__device__ int   g_dst_mask[BEAM];   // per canonical slot: bitmask of dest beams sharing its source

__device__ __forceinline__ bool cand_gt(float av, int ai, float bv, int bi) {
    // strictly greater value wins; on exact tie, lower index wins (jax.lax.top_k order)
    return (av > bv) || (av == bv && ai < bi);
}

// ---------------------------------------------------------------------------
// Kernel 1: per-chunk online softmax (m, s) + top-8.
// 256 threads/block now (halves the serial per-thread expf chain).
// grid = BEAM*CHUNKS = 256 blocks.
// ---------------------------------------------------------------------------
__global__ void __launch_bounds__(K1_THREADS) chunk_topk_kernel(const float* __restrict__ logits) {
    const int chunk = blockIdx.x & (CHUNKS - 1);
    const int r     = blockIdx.x >> 5;
    const int tid   = threadIdx.x;
    const int start = chunk * CHUNK_SZ;
    const int end   = min(start + CHUNK_SZ, VOCAB);
    const float* row = logits + (long long)r * VOCAB;

    float m = -INFINITY, s = 0.0f;
    float lv[TOPK];
    int   li[TOPK];
#pragma unroll
    for (int j = 0; j < TOPK; j++) { lv[j] = -INFINITY; li[j] = 0x7fffffff; }

    for (int i = start + tid; i < end; i += K1_THREADS) {
        float v = row[i];
        if (v > m) { s = s * __expf(m - v) + 1.0f; m = v; }
        else       { s += __expf(v - m); }
        if (cand_gt(v, i, lv[TOPK - 1], li[TOPK - 1])) {
            int j = TOPK - 1;
            while (j > 0 && cand_gt(v, i, lv[j - 1], li[j - 1])) {
                lv[j] = lv[j - 1]; li[j] = li[j - 1]; j--;
            }
            lv[j] = v; li[j] = i;
        }
    }

    __shared__ float sm[K1_THREADS], ss[K1_THREADS];
    sm[tid] = m; ss[tid] = s;
    __syncthreads();
    for (int st = K1_THREADS / 2; st > 0; st >>= 1) {
        if (tid < st) {
            float m1 = sm[tid], s1 = ss[tid];
            float m2 = sm[tid + st], s2 = ss[tid + st];
            float M = fmaxf(m1, m2);
            float S = ((m1 > -INFINITY) ? s1 * __expf(m1 - M) : 0.0f)
                    + ((m2 > -INFINITY) ? s2 * __expf(m2 - M) : 0.0f);
            sm[tid] = M; ss[tid] = S;
        }
        __syncthreads();
    }

    __shared__ float sv[K1_THREADS * TOPK];
    __shared__ int   si[K1_THREADS * TOPK];
#pragma unroll
    for (int j = 0; j < TOPK; j++) { sv[tid * TOPK + j] = lv[j]; si[tid * TOPK + j] = li[j]; }
    __syncthreads();

    for (int step = 1; step < K1_THREADS; step <<= 1) {
        if ((tid & (2 * step - 1)) == 0) {
            float* A  = &sv[tid * TOPK];
            int*   Ai = &si[tid * TOPK];
            float* B  = &sv[(tid + step) * TOPK];
            int*   Bi = &si[(tid + step) * TOPK];
            float mv[TOPK]; int mi[TOPK];
            int pa = 0, pb = 0;
#pragma unroll
            for (int j = 0; j < TOPK; j++) {
                if (cand_gt(A[pa], Ai[pa], B[pb], Bi[pb])) { mv[j] = A[pa]; mi[j] = Ai[pa]; pa++; }
                else                                        { mv[j] = B[pb]; mi[j] = Bi[pb]; pb++; }
            }
#pragma unroll
            for (int j = 0; j < TOPK; j++) { A[j] = mv[j]; Ai[j] = mi[j]; }
        }
        __syncthreads();
    }

    if (tid == 0) {
        g_part_m[blockIdx.x] = sm[0];
        g_part_s[blockIdx.x] = ss[0];
    }
    if (tid < TOPK) {
        g_part_val[blockIdx.x * TOPK + tid] = sv[tid];
        g_part_idx[blockIdx.x * TOPK + tid] = si[tid];
    }
}

// ---------------------------------------------------------------------------
// Kernel 2: per-row merge (LSE + top-8), global beam top-8, dedupe masks,
// small outputs.
// ---------------------------------------------------------------------------
__global__ void select_kernel(const int* __restrict__ save_id,
                              const float* __restrict__ prev_prob,
                              float* __restrict__ out) {
    __shared__ float cv[BEAM * TOPK];
    __shared__ int   ci[BEAM * TOPK];
    __shared__ int   s_beam[BEAM];
    __shared__ int   s_tbi[BEAM];
    __shared__ float s_prob[BEAM];

    const int tid = threadIdx.x;

    if (tid < BEAM) {
        const int r = tid;
        float M = -INFINITY;
        for (int c = 0; c < CHUNKS; c++) M = fmaxf(M, g_part_m[r * CHUNKS + c]);
        float S = 0.0f;
        for (int c = 0; c < CHUNKS; c++) {
            float pm = g_part_m[r * CHUNKS + c];
            if (pm > -INFINITY) S += g_part_s[r * CHUNKS + c] * __expf(pm - M);
        }
        const float lse = M + logf(S);

        const float* pv = &g_part_val[r * CHUNKS * TOPK];
        const int*   pi = &g_part_idx[r * CHUNKS * TOPK];
        int chosen[TOPK];
        for (int k = 0; k < TOPK; k++) {
            int best = -1;
            float bv = -INFINITY; int bidx = 0x7fffffff;
            for (int i = 0; i < CHUNKS * TOPK; i++) {
                bool skip = false;
                for (int p = 0; p < k; p++) if (chosen[p] == i) { skip = true; break; }
                if (skip) continue;
                if (best < 0 || cand_gt(pv[i], pi[i], bv, bidx)) {
                    best = i; bv = pv[i]; bidx = pi[i];
                }
            }
            chosen[k] = best;
            cv[r * TOPK + k] = bv - lse + prev_prob[r];
            ci[r * TOPK + k] = bidx;
        }
    }
    __syncthreads();

    if (tid == 0) {
        bool used[BEAM * TOPK];
        for (int i = 0; i < BEAM * TOPK; i++) used[i] = false;
        for (int b = 0; b < BEAM; b++) {
            int best = -1;
            for (int i = 0; i < BEAM * TOPK; i++) {
                if (used[i]) continue;
                if (best < 0 || cv[i] > cv[best]) best = i;
            }
            used[best] = true;
            s_beam[b] = best >> 3;
            s_tbi[b]  = ci[best];
            s_prob[b] = cv[best];
            g_beam_index[b] = best >> 3;
        }
        // dedupe masks: slot u is canonical iff no earlier dest has the same
        // source; its mask holds ALL dests (incl. itself) sharing that source.
        for (int u = 0; u < BEAM; u++) {
            int mask = 0;
            bool canonical = true;
            for (int p = 0; p < u; p++)
                if (s_beam[p] == s_beam[u]) { canonical = false; break; }
            if (canonical)
                for (int b = u; b < BEAM; b++)
                    if (s_beam[b] == s_beam[u]) mask |= (1 << b);
            g_dst_mask[u] = mask;
        }
    }
    __syncthreads();

    for (int i = tid; i < BEAM * (HIST + 1); i += blockDim.x) {
        int b = i / (HIST + 1);
        int c = i % (HIST + 1);
        int val = (c < HIST) ? save_id[s_beam[b] * HIST + c] : s_tbi[b];
        out[OFF_SAVE + i] = (float)val;
    }
    if (tid < BEAM) {
        out[OFF_PROB + tid] = s_prob[tid];
        out[OFF_TBI + tid]  = (float)s_tbi[tid];
    }
    if (tid == 0) out[OFF_MAX] = (float)s_tbi[0];
}

// ---------------------------------------------------------------------------
// Kernel 3: source-dedupe gather with register fan-out.
// blockIdx = chunk_global*8 + slot. Canonical slots read their 16KB chunk
// from DRAM ONCE (4 independent float4/thread) and store it to every dest
// beam in their mask (all stores independent). Duplicate slots exit.
// DRAM traffic: (k_unique/8)*1.07GB read + 1.07GB write — guaranteed, no
// reliance on L2 timing. k=8 degenerates to the plain per-beam copy.
// ---------------------------------------------------------------------------
__global__ void __launch_bounds__(256) gather_kernel(const float4* __restrict__ kv,
                                                     float4* __restrict__ out) {
    __shared__ int smask[BEAM];
    __shared__ int ssrc[BEAM];
    if (threadIdx.x < BEAM) {
        smask[threadIdx.x] = g_dst_mask[threadIdx.x];
        ssrc[threadIdx.x]  = g_beam_index[threadIdx.x];
    }
    __syncthreads();

    const int u            = blockIdx.x & 7;
    const int mask         = smask[u];
    if (mask == 0) return;                       // duplicate slot: no work

    const int chunk_global = blockIdx.x >> 3;    // 0..8191
    const int grp          = chunk_global & (GRPS_PER_LAYER - 1);
    const int l            = chunk_global >> 8;

    const long long lbase = (long long)l * BEAM * SLAB_F4;
    const int off = grp * 1024 + threadIdx.x;

    const float4* src = kv + (lbase + (long long)ssrc[u] * SLAB_F4 + off);
    float4 v0 = src[0];
    float4 v1 = src[256];
    float4 v2 = src[512];
    float4 v3 = src[768];

#pragma unroll
    for (int b = 0; b < BEAM; b++) {
        if (mask & (1 << b)) {
            float4* dst = out + (lbase + (long long)b * SLAB_F4 + off);
            dst[0]   = v0;
            dst[256] = v1;
            dst[512] = v2;
            dst[768] = v3;
        }
    }
}

// ---------------------------------------------------------------------------
extern "C" void kernel_launch(void* const* d_in, const int* in_sizes, int n_in,
                              void* d_out, int out_size) {
    const float* kv_cache  = (const float*)d_in[0];
    const float* logits    = (const float*)d_in[1];
    const int*   save_id   = (const int*)d_in[2];
    const float* prev_prob = (const float*)d_in[3];
    float* out = (float*)d_out;

    chunk_topk_kernel<<<BEAM * CHUNKS, K1_THREADS>>>(logits);
    select_kernel<<<1, 256>>>(save_id, prev_prob, out);
    gather_kernel<<<CHUNK_GLOBAL * BEAM, 256>>>(
        (const float4*)kv_cache, (float4*)(out + OFF_KV));
}

// round 14
// speedup vs baseline: 2.2236x; 2.0722x over previous
#include <cuda_runtime.h>
#include <math.h>

#define L_LAYERS 32
#define BEAM 8
#define KV2 2
#define HEADS 8
#define SEQ 1024
#define HDIM 64
#define VOCAB 50257
#define HIST 128
#define TOPK 8
#define CHUNKS 32
#define CHUNK_SZ 1571          // 32*1571 = 50272 >= 50257
#define K1_THREADS 256
#define K1_BLOCKS (BEAM * CHUNKS)   // 256

// per-(l,b) slab: KV2*HEADS*SEQ*HDIM floats = 1,048,576 floats = 262,144 float4
#define SLAB_F4 262144
#define GRPS_PER_LAYER 256     // 262144 f4 / 1024 f4 per block
#define CHUNK_GLOBAL (L_LAYERS * GRPS_PER_LAYER)   // 8192

// output offsets (float32 elements, concatenated in reference return order)
#define OFF_KV   0LL
#define OFF_SAVE 268435456LL
#define OFF_PROB 268436488LL
#define OFF_TBI  268436496LL
#define OFF_MAX  268436504LL

// device-global scratch (no allocations allowed)
__device__ float g_part_m[BEAM * CHUNKS];
__device__ float g_part_s[BEAM * CHUNKS];
__device__ float g_part_val[BEAM * CHUNKS * TOPK];
__device__ int   g_part_idx[BEAM * CHUNKS * TOPK];
__device__ int   g_beam_index[BEAM];
__device__ int   g_dst_mask[BEAM];
__device__ unsigned int g_done = 0;   // self-resetting completion counter

__device__ __forceinline__ bool cand_gt(float av, int ai, float bv, int bi) {
    // strictly greater value wins; on exact tie, lower index wins (jax.lax.top_k order)
    return (av > bv) || (av == bv && ai < bi);
}

// ---------------------------------------------------------------------------
// Fused kernel: per-chunk online softmax + top-8 partials; LAST block merges
// (warp-per-row), does global beam selection, writes small outputs.
// grid = 256 blocks x 256 threads.
// ---------------------------------------------------------------------------
__global__ void __launch_bounds__(K1_THREADS)
topk_select_kernel(const float* __restrict__ logits,
                   const int* __restrict__ save_id,
                   const float* __restrict__ prev_prob,
                   float* __restrict__ out) {
    const int chunk = blockIdx.x & (CHUNKS - 1);
    const int r     = blockIdx.x >> 5;
    const int tid   = threadIdx.x;
    const int start = chunk * CHUNK_SZ;
    const int end   = min(start + CHUNK_SZ, VOCAB);
    const float* row = logits + (long long)r * VOCAB;

    float m = -INFINITY, s = 0.0f;
    float lv[TOPK];
    int   li[TOPK];
#pragma unroll
    for (int j = 0; j < TOPK; j++) { lv[j] = -INFINITY; li[j] = 0x7fffffff; }

    for (int i = start + tid; i < end; i += K1_THREADS) {
        float v = row[i];
        if (v > m) { s = s * __expf(m - v) + 1.0f; m = v; }
        else       { s += __expf(v - m); }
        if (cand_gt(v, i, lv[TOPK - 1], li[TOPK - 1])) {
            int j = TOPK - 1;
            while (j > 0 && cand_gt(v, i, lv[j - 1], li[j - 1])) {
                lv[j] = lv[j - 1]; li[j] = li[j - 1]; j--;
            }
            lv[j] = v; li[j] = i;
        }
    }

    __shared__ float sm[K1_THREADS], ss[K1_THREADS];
    sm[tid] = m; ss[tid] = s;
    __syncthreads();
    for (int st = K1_THREADS / 2; st > 0; st >>= 1) {
        if (tid < st) {
            float m1 = sm[tid], s1 = ss[tid];
            float m2 = sm[tid + st], s2 = ss[tid + st];
            float M = fmaxf(m1, m2);
            float S = ((m1 > -INFINITY) ? s1 * __expf(m1 - M) : 0.0f)
                    + ((m2 > -INFINITY) ? s2 * __expf(m2 - M) : 0.0f);
            sm[tid] = M; ss[tid] = S;
        }
        __syncthreads();
    }

    __shared__ float sv[K1_THREADS * TOPK];
    __shared__ int   si[K1_THREADS * TOPK];
#pragma unroll
    for (int j = 0; j < TOPK; j++) { sv[tid * TOPK + j] = lv[j]; si[tid * TOPK + j] = li[j]; }
    __syncthreads();

    for (int step = 1; step < K1_THREADS; step <<= 1) {
        if ((tid & (2 * step - 1)) == 0) {
            float* A  = &sv[tid * TOPK];
            int*   Ai = &si[tid * TOPK];
            float* B  = &sv[(tid + step) * TOPK];
            int*   Bi = &si[(tid + step) * TOPK];
            float mv[TOPK]; int mi[TOPK];
            int pa = 0, pb = 0;
#pragma unroll
            for (int j = 0; j < TOPK; j++) {
                if (cand_gt(A[pa], Ai[pa], B[pb], Bi[pb])) { mv[j] = A[pa]; mi[j] = Ai[pa]; pa++; }
                else                                        { mv[j] = B[pb]; mi[j] = Bi[pb]; pb++; }
            }
#pragma unroll
            for (int j = 0; j < TOPK; j++) { A[j] = mv[j]; Ai[j] = mi[j]; }
        }
        __syncthreads();
    }

    if (tid == 0) {
        g_part_m[blockIdx.x] = sm[0];
        g_part_s[blockIdx.x] = ss[0];
    }
    if (tid < TOPK) {
        g_part_val[blockIdx.x * TOPK + tid] = sv[tid];
        g_part_idx[blockIdx.x * TOPK + tid] = si[tid];
    }

    // -------- last-block merge --------
    __shared__ bool is_last;
    __threadfence();
    if (tid == 0) {
        unsigned int prev = atomicAdd(&g_done, 1u);
        is_last = (prev == (unsigned)(K1_BLOCKS - 1));
    }
    __syncthreads();
    if (!is_last) return;
    __threadfence();   // acquire side

    __shared__ float cv[BEAM * TOPK];
    __shared__ int   ci[BEAM * TOPK];
    __shared__ int   s_beam[BEAM];
    __shared__ int   s_tbi[BEAM];
    __shared__ float s_prob[BEAM];

    const int wid  = tid >> 5;
    const int lane = tid & 31;

    if (wid < BEAM) {
        const int rr = wid;
        // lane l owns chunk l's (m, s)
        float M = g_part_m[rr * CHUNKS + lane];
        float S = g_part_s[rr * CHUNKS + lane];
#pragma unroll
        for (int o = 16; o > 0; o >>= 1) {
            float M2 = __shfl_down_sync(0xffffffffu, M, o);
            float S2 = __shfl_down_sync(0xffffffffu, S, o);
            float Mn = fmaxf(M, M2);
            float Sn = ((M  > -INFINITY) ? S  * __expf(M  - Mn) : 0.0f)
                     + ((M2 > -INFINITY) ? S2 * __expf(M2 - Mn) : 0.0f);
            M = Mn; S = Sn;
        }
        float lse = M + logf(S);
        lse = __shfl_sync(0xffffffffu, lse, 0);
        const float pprev = prev_prob[rr];

        // lane l holds candidates l + 32*j, j=0..7
        float qv[8];
        int   qi[8];
        bool  used[8];
#pragma unroll
        for (int j = 0; j < 8; j++) {
            int idx = rr * (CHUNKS * TOPK) + lane + 32 * j;
            qv[j] = g_part_val[idx];
            qi[j] = g_part_idx[idx];
            used[j] = false;
        }

        for (int k = 0; k < TOPK; k++) {
            // local best among unused
            float bv = -INFINITY; int bidx = 0x7fffffff; int bj = -1;
#pragma unroll
            for (int j = 0; j < 8; j++) {
                if (!used[j] && cand_gt(qv[j], qi[j], bv, bidx)) {
                    bv = qv[j]; bidx = qi[j]; bj = j;
                }
            }
            int bl = lane;
            // warp argmax
#pragma unroll
            for (int o = 16; o > 0; o >>= 1) {
                float ov = __shfl_down_sync(0xffffffffu, bv, o);
                int   oi = __shfl_down_sync(0xffffffffu, bidx, o);
                int   ol = __shfl_down_sync(0xffffffffu, bl, o);
                int   oj = __shfl_down_sync(0xffffffffu, bj, o);
                if (cand_gt(ov, oi, bv, bidx)) { bv = ov; bidx = oi; bl = ol; bj = oj; }
            }
            // broadcast winner
            bv   = __shfl_sync(0xffffffffu, bv, 0);
            bidx = __shfl_sync(0xffffffffu, bidx, 0);
            bl   = __shfl_sync(0xffffffffu, bl, 0);
            bj   = __shfl_sync(0xffffffffu, bj, 0);
            if (lane == bl) used[bj] = true;
            if (lane == 0) {
                cv[rr * TOPK + k] = bv - lse + pprev;
                ci[rr * TOPK + k] = bidx;
            }
        }
    }
    __syncthreads();

    if (tid == 0) {
        bool usedc[BEAM * TOPK];
        for (int i = 0; i < BEAM * TOPK; i++) usedc[i] = false;
        for (int b = 0; b < BEAM; b++) {
            int best = -1;
            for (int i = 0; i < BEAM * TOPK; i++) {
                if (usedc[i]) continue;
                if (best < 0 || cv[i] > cv[best]) best = i;  // strict > keeps lower flat index
            }
            usedc[best] = true;
            s_beam[b] = best >> 3;
            s_tbi[b]  = ci[best];
            s_prob[b] = cv[best];
            g_beam_index[b] = best >> 3;
        }
        // dedupe masks (free insurance; degenerates to identity when all distinct)
        for (int u = 0; u < BEAM; u++) {
            int mask = 0;
            bool canonical = true;
            for (int p = 0; p < u; p++)
                if (s_beam[p] == s_beam[u]) { canonical = false; break; }
            if (canonical)
                for (int b = u; b < BEAM; b++)
                    if (s_beam[b] == s_beam[u]) mask |= (1 << b);
            g_dst_mask[u] = mask;
        }
    }
    __syncthreads();

    for (int i = tid; i < BEAM * (HIST + 1); i += blockDim.x) {
        int b = i / (HIST + 1);
        int c = i % (HIST + 1);
        int val = (c < HIST) ? save_id[s_beam[b] * HIST + c] : s_tbi[b];
        out[OFF_SAVE + i] = (float)val;
    }
    if (tid < BEAM) {
        out[OFF_PROB + tid] = s_prob[tid];
        out[OFF_TBI + tid]  = (float)s_tbi[tid];
    }
    if (tid == 0) out[OFF_MAX] = (float)s_tbi[0];

    __syncthreads();
    if (tid == 0) g_done = 0;   // reset for next graph replay
}

// ---------------------------------------------------------------------------
// Gather: measured-best structure (65536 blocks, MLP=4) + STREAMING cache
// hints (__ldcs reads, __stcs writes). No data reuse exists, so evict-first
// costs nothing; hypothesis under test: less L2 churn -> higher mixed-stream
// bandwidth. Dedupe masks kept (no-op when sources distinct).
// ---------------------------------------------------------------------------
__global__ void __launch_bounds__(256) gather_kernel(const float4* __restrict__ kv,
                                                     float4* __restrict__ out) {
    __shared__ int smask[BEAM];
    __shared__ int ssrc[BEAM];
    if (threadIdx.x < BEAM) {
        smask[threadIdx.x] = g_dst_mask[threadIdx.x];
        ssrc[threadIdx.x]  = g_beam_index[threadIdx.x];
    }
    __syncthreads();

    const int u    = blockIdx.x & 7;
    const int mask = smask[u];
    if (mask == 0) return;

    const int chunk_global = blockIdx.x >> 3;
    const int grp          = chunk_global & (GRPS_PER_LAYER - 1);
    const int l            = chunk_global >> 8;

    const long long lbase = (long long)l * BEAM * SLAB_F4;
    const int off = grp * 1024 + threadIdx.x;

    const float4* src = kv + (lbase + (long long)ssrc[u] * SLAB_F4 + off);
    float4 v0 = __ldcs(src + 0);
    float4 v1 = __ldcs(src + 256);
    float4 v2 = __ldcs(src + 512);
    float4 v3 = __ldcs(src + 768);

#pragma unroll
    for (int b = 0; b < BEAM; b++) {
        if (mask & (1 << b)) {
            float4* dst = out + (lbase + (long long)b * SLAB_F4 + off);
            __stcs(dst + 0,   v0);
            __stcs(dst + 256, v1);
            __stcs(dst + 512, v2);
            __stcs(dst + 768, v3);
        }
    }
}

// ---------------------------------------------------------------------------
extern "C" void kernel_launch(void* const* d_in, const int* in_sizes, int n_in,
                              void* d_out, int out_size) {
    const float* kv_cache  = (const float*)d_in[0];
    const float* logits    = (const float*)d_in[1];
    const int*   save_id   = (const int*)d_in[2];
    const float* prev_prob = (const float*)d_in[3];
    float* out = (float*)d_out;

    topk_select_kernel<<<K1_BLOCKS, K1_THREADS>>>(logits, save_id, prev_prob, out);
    gather_kernel<<<CHUNK_GLOBAL * BEAM, 256>>>(
        (const float4*)kv_cache, (float4*)(out + OFF_KV));
}